// round 12
// baseline (speedup 1.0000x reference)
#include <cuda_runtime.h>
#include <cuda_bf16.h>
#include <math.h>

#define N_NODES 50000
#define N_EDGES 500000
#define NFEAT   128
#define NHID    128
#define NOUT    16

// ---------------- device scratch (static allocation is allowed) ----------------
__device__ float g_deg[N_NODES];
__device__ float g_dinv[N_NODES];
__device__ int   g_count[N_NODES];
__device__ int   g_rowptr[N_NODES];
__device__ int   g_fill[N_NODES];
__device__ int   g_total;
__device__ int   g_csr_src[N_EDGES];
__device__ float g_csr_norm[N_EDGES];
__device__ float g_xw[(size_t)N_NODES * 128];   // x @ W scratch (also holds 50000x16 for layer 3)
__device__ float g_h[(size_t)N_NODES * 128];    // hidden activations

// ---------------- graph preprocessing ----------------
__global__ void init_nodes_kernel() {
    int i = blockIdx.x * blockDim.x + threadIdx.x;
    if (i == 0) g_total = 0;
    if (i < N_NODES) { g_deg[i] = 1.0f; g_count[i] = 0; }   // self-loop weight 1
}

__global__ void edge_deg_kernel(const int* __restrict__ dst, const float* __restrict__ ew) {
    int e = blockIdx.x * blockDim.x + threadIdx.x;
    if (e < N_EDGES) {
        int d = dst[e];
        atomicAdd(&g_deg[d], ew[e]);
        atomicAdd(&g_count[d], 1);
    }
}

__global__ void node_dinv_kernel() {
    int i = blockIdx.x * blockDim.x + threadIdx.x;
    if (i < N_NODES) g_dinv[i] = rsqrtf(g_deg[i]);   // deg >= 1 always
}

// Segment allocation WITHOUT a global scan: each 256-node block does a local
// exclusive scan (warp shfl + smem) and grabs its base with one atomicAdd on a
// global cursor. Segments land in arbitrary block order — irrelevant, since
// each node's CSR segment is still contiguous and exact.
__global__ __launch_bounds__(256) void alloc_kernel() {
    int i = blockIdx.x * blockDim.x + threadIdx.x;
    int lane = threadIdx.x & 31, wid = threadIdx.x >> 5;
    int c = (i < N_NODES) ? g_count[i] : 0;
    // warp inclusive scan
    int p = c;
#pragma unroll
    for (int o = 1; o < 32; o <<= 1) {
        int v = __shfl_up_sync(0xffffffffu, p, o);
        if (lane >= o) p += v;
    }
    __shared__ int wsum[8];
    __shared__ int base;
    if (lane == 31) wsum[wid] = p;
    __syncthreads();
    if (threadIdx.x == 0) {
        int s = 0;
#pragma unroll
        for (int w = 0; w < 8; w++) { int t = wsum[w]; wsum[w] = s; s += t; }
        base = atomicAdd(&g_total, s);
    }
    __syncthreads();
    int off = base + wsum[wid] + (p - c);   // exclusive prefix within block + block base
    if (i < N_NODES) { g_rowptr[i] = off; g_fill[i] = off; }
}

__global__ void edge_scatter_kernel(const int* __restrict__ src, const int* __restrict__ dst,
                                    const float* __restrict__ ew) {
    int e = blockIdx.x * blockDim.x + threadIdx.x;
    if (e < N_EDGES) {
        int s = src[e], d = dst[e];
        int p = atomicAdd(&g_fill[d], 1);
        g_csr_src[p]  = s;
        g_csr_norm[p] = g_dinv[s] * ew[e] * g_dinv[d];
    }
}

// ---------------- SGEMM: [M,128] @ [128,128] -> [M,128] ----------------
// BM=128, BK=16, 256 threads, 8x8 micro-tile per thread.
__global__ __launch_bounds__(256) void gemm_f128(const float* __restrict__ A,
                                                 const float* __restrict__ W,
                                                 float* __restrict__ C, int M) {
    const int K = 128, N = 128, BM = 128, BK = 16;
    __shared__ float xs[BK][BM];   // A tile transposed
    __shared__ float ws[BK][N];
    int tid = threadIdx.x;
    int tx = tid & 15;    // col group (8 cols)
    int ty = tid >> 4;    // row group (8 rows)
    int rowBase = blockIdx.x * BM;

    float acc[8][8];
#pragma unroll
    for (int i = 0; i < 8; i++)
#pragma unroll
        for (int j = 0; j < 8; j++) acc[i][j] = 0.0f;

    int lr = tid >> 2;            // 0..63
    int lk = (tid & 3) * 4;       // 0,4,8,12
    int wkk = tid >> 4;           // 0..15
    int wnn = (tid & 15) * 8;     // 0..120

    for (int k0 = 0; k0 < K; k0 += BK) {
#pragma unroll
        for (int rr = 0; rr < 2; rr++) {
            int rl = lr + rr * 64;
            int row = rowBase + rl;
            float4 va = (row < M) ? *(const float4*)&A[(size_t)row * K + k0 + lk]
                                  : make_float4(0.f, 0.f, 0.f, 0.f);
            xs[lk + 0][rl] = va.x; xs[lk + 1][rl] = va.y;
            xs[lk + 2][rl] = va.z; xs[lk + 3][rl] = va.w;
        }
        const float* wp = &W[(size_t)(k0 + wkk) * N + wnn];
        float4 w0 = *(const float4*)wp;
        float4 w1 = *(const float4*)(wp + 4);
        *(float4*)&ws[wkk][wnn]     = w0;
        *(float4*)&ws[wkk][wnn + 4] = w1;
        __syncthreads();
#pragma unroll
        for (int k = 0; k < BK; k++) {
            float av[8], bv[8];
            *(float4*)&av[0] = *(const float4*)&xs[k][ty * 8];
            *(float4*)&av[4] = *(const float4*)&xs[k][ty * 8 + 4];
            *(float4*)&bv[0] = *(const float4*)&ws[k][tx * 8];
            *(float4*)&bv[4] = *(const float4*)&ws[k][tx * 8 + 4];
#pragma unroll
            for (int i = 0; i < 8; i++)
#pragma unroll
                for (int j = 0; j < 8; j++)
                    acc[i][j] = fmaf(av[i], bv[j], acc[i][j]);
        }
        __syncthreads();
    }
#pragma unroll
    for (int i = 0; i < 8; i++) {
        int r = rowBase + ty * 8 + i;
        if (r < M) {
            *(float4*)&C[(size_t)r * N + tx * 8]     = *(float4*)&acc[i][0];
            *(float4*)&C[(size_t)r * N + tx * 8 + 4] = *(float4*)&acc[i][4];
        }
    }
}

// ---------------- SGEMM: [M,128] @ [128,16] -> [M,16] ----------------
__global__ __launch_bounds__(256) void gemm_f16k(const float* __restrict__ A,
                                                 const float* __restrict__ W,
                                                 float* __restrict__ C, int M) {
    const int K = 128, N = 16, BM = 256, BK = 16;
    __shared__ float xs[BK][BM];
    __shared__ float ws[BK][N];
    int tid = threadIdx.x;
    int ty = tid >> 2;      // 0..63 -> rows ty*4..+3
    int tx = tid & 3;       // 0..3  -> cols tx*4..+3
    int rowBase = blockIdx.x * BM;
    float acc[4][4];
#pragma unroll
    for (int i = 0; i < 4; i++)
#pragma unroll
        for (int j = 0; j < 4; j++) acc[i][j] = 0.0f;

    int lr = tid >> 2;
    int lk = (tid & 3) * 4;

    for (int k0 = 0; k0 < K; k0 += BK) {
#pragma unroll
        for (int rr = 0; rr < 4; rr++) {
            int rl = lr + rr * 64;
            int row = rowBase + rl;
            float4 va = (row < M) ? *(const float4*)&A[(size_t)row * K + k0 + lk]
                                  : make_float4(0.f, 0.f, 0.f, 0.f);
            xs[lk + 0][rl] = va.x; xs[lk + 1][rl] = va.y;
            xs[lk + 2][rl] = va.z; xs[lk + 3][rl] = va.w;
        }
        if (tid < 64) {
            int kk = tid >> 2;
            int nn = (tid & 3) * 4;
            *(float4*)&ws[kk][nn] = *(const float4*)&W[(size_t)(k0 + kk) * N + nn];
        }
        __syncthreads();
#pragma unroll
        for (int k = 0; k < BK; k++) {
            float4 a = *(const float4*)&xs[k][ty * 4];
            float4 b = *(const float4*)&ws[k][tx * 4];
            float av[4] = {a.x, a.y, a.z, a.w};
            float bv[4] = {b.x, b.y, b.z, b.w};
#pragma unroll
            for (int i = 0; i < 4; i++)
#pragma unroll
                for (int j = 0; j < 4; j++)
                    acc[i][j] = fmaf(av[i], bv[j], acc[i][j]);
        }
        __syncthreads();
    }
#pragma unroll
    for (int i = 0; i < 4; i++) {
        int r = rowBase + ty * 4 + i;
        if (r < M) {
            float4 o = {acc[i][0], acc[i][1], acc[i][2], acc[i][3]};
            *(float4*)&C[(size_t)r * N + tx * 4] = o;
        }
    }
}

// ---------------- aggregation: warp per node, 128 features ----------------
__global__ __launch_bounds__(256) void agg128_kernel(const float4* __restrict__ xw,
                                                     const float* __restrict__ bias,
                                                     float4* __restrict__ out, int do_relu) {
    int gw = (blockIdx.x * blockDim.x + threadIdx.x) >> 5;
    int lane = threadIdx.x & 31;
    if (gw >= N_NODES) return;
    int i = gw;
    float di = g_dinv[i];
    float s = di * di;                         // self-loop coeff d^-1
    float4 v = xw[(size_t)i * 32 + lane];
    float4 bb = ((const float4*)bias)[lane];
    float4 acc;
    acc.x = fmaf(v.x, s, bb.x); acc.y = fmaf(v.y, s, bb.y);
    acc.z = fmaf(v.z, s, bb.z); acc.w = fmaf(v.w, s, bb.w);

    int e0 = g_rowptr[i], e1 = e0 + g_count[i];
    for (int eb = e0; eb < e1; eb += 32) {
        int idx = eb + lane;
        int sj = 0; float wj = 0.0f;
        if (idx < e1) { sj = g_csr_src[idx]; wj = g_csr_norm[idx]; }
        int cnt = min(32, e1 - eb);
        for (int j = 0; j < cnt; j++) {
            int   sk = __shfl_sync(0xffffffffu, sj, j);
            float wk = __shfl_sync(0xffffffffu, wj, j);
            float4 u = __ldg(&xw[(size_t)sk * 32 + lane]);
            acc.x = fmaf(wk, u.x, acc.x);
            acc.y = fmaf(wk, u.y, acc.y);
            acc.z = fmaf(wk, u.z, acc.z);
            acc.w = fmaf(wk, u.w, acc.w);
        }
    }
    if (do_relu) {
        acc.x = fmaxf(acc.x, 0.f); acc.y = fmaxf(acc.y, 0.f);
        acc.z = fmaxf(acc.z, 0.f); acc.w = fmaxf(acc.w, 0.f);
    }
    out[(size_t)i * 32 + lane] = acc;
}

// ---------------- aggregation + log_softmax: warp per node, 16 features ----------------
__global__ __launch_bounds__(256) void agg16_lsm_kernel(const float* __restrict__ xw,
                                                        const float* __restrict__ bias,
                                                        float* __restrict__ out) {
    int gw = (blockIdx.x * blockDim.x + threadIdx.x) >> 5;
    int lane = threadIdx.x & 31;
    if (gw >= N_NODES) return;
    int i = gw;
    float di = g_dinv[i];
    float s = di * di;
    float acc = 0.0f;
    if (lane < 16) acc = fmaf(xw[(size_t)i * 16 + lane], s, bias[lane]);

    int e0 = g_rowptr[i], e1 = e0 + g_count[i];
    for (int eb = e0; eb < e1; eb += 32) {
        int idx = eb + lane;
        int sj = 0; float wj = 0.0f;
        if (idx < e1) { sj = g_csr_src[idx]; wj = g_csr_norm[idx]; }
        int cnt = min(32, e1 - eb);
        for (int j = 0; j < cnt; j++) {
            int   sk = __shfl_sync(0xffffffffu, sj, j);
            float wk = __shfl_sync(0xffffffffu, wj, j);
            if (lane < 16)
                acc = fmaf(wk, __ldg(&xw[(size_t)sk * 16 + lane]), acc);
        }
    }
    // log_softmax across the 16 feature lanes (xor<16 keeps lanes 0-15 in-group)
    float v = (lane < 16) ? acc : -INFINITY;
    float m = v;
#pragma unroll
    for (int o = 8; o > 0; o >>= 1) m = fmaxf(m, __shfl_xor_sync(0xffffffffu, m, o));
    float ee = (lane < 16) ? expf(acc - m) : 0.0f;
    float ss = ee;
#pragma unroll
    for (int o = 8; o > 0; o >>= 1) ss += __shfl_xor_sync(0xffffffffu, ss, o);
    if (lane < 16) out[(size_t)i * 16 + lane] = acc - m - logf(ss);
}

// ---------------- launch ----------------
extern "C" void kernel_launch(void* const* d_in, const int* in_sizes, int n_in,
                              void* d_out, int out_size) {
    const float* x    = (const float*)d_in[0];
    const int*   esrc = (const int*)d_in[1];
    const int*   edst = (const int*)d_in[2];
    const float* ew   = (const float*)d_in[3];
    const float* W1   = (const float*)d_in[4];
    const float* b1   = (const float*)d_in[5];
    const float* W2   = (const float*)d_in[6];
    const float* b2   = (const float*)d_in[7];
    const float* W3   = (const float*)d_in[8];
    const float* b3   = (const float*)d_in[9];
    float* out = (float*)d_out;

    float *p_xw = nullptr, *p_h = nullptr;
    cudaGetSymbolAddress((void**)&p_xw, g_xw);
    cudaGetSymbolAddress((void**)&p_h,  g_h);

    const int NB_NODE = (N_NODES + 255) / 256;       // 196
    const int NB_EDGE = (N_EDGES + 255) / 256;       // 1954
    const int NB_WARP = (N_NODES * 32 + 255) / 256;  // 6250 (warp per node)
    const int NB_G128 = (N_NODES + 127) / 128;       // 391
    const int NB_G16  = (N_NODES + 255) / 256;       // 196

    // graph preprocessing (rebuilt every call; deterministic work)
    init_nodes_kernel<<<NB_NODE, 256>>>();
    edge_deg_kernel<<<NB_EDGE, 256>>>(edst, ew);
    node_dinv_kernel<<<NB_NODE, 256>>>();
    alloc_kernel<<<NB_NODE, 256>>>();
    edge_scatter_kernel<<<NB_EDGE, 256>>>(esrc, edst, ew);

    // layer 1: h = relu(agg(x @ W1) + b1)
    gemm_f128<<<NB_G128, 256>>>(x, W1, p_xw, N_NODES);
    agg128_kernel<<<NB_WARP, 256>>>((const float4*)p_xw, b1, (float4*)p_h, 1);

    // layer 2: h = relu(agg(h @ W2) + b2)
    gemm_f128<<<NB_G128, 256>>>(p_h, W2, p_xw, N_NODES);
    agg128_kernel<<<NB_WARP, 256>>>((const float4*)p_xw, b2, (float4*)p_h, 1);

    // layer 3: out = log_softmax(agg(h @ W3) + b3)
    gemm_f16k<<<NB_G16, 256>>>(p_h, W3, p_xw, N_NODES);
    agg16_lsm_kernel<<<NB_WARP, 256>>>(p_xw, b3, out);
}

// round 13
// speedup vs baseline: 1.4538x; 1.4538x over previous
#include <cuda_runtime.h>
#include <cuda_bf16.h>
#include <math.h>

#define N_NODES 50000
#define N_EDGES 500000
#define NFEAT   128
#define NHID    128
#define NOUT    16

// ---------------- device scratch (static allocation is allowed) ----------------
__device__ float g_deg[N_NODES];
__device__ float g_dinv[N_NODES];
__device__ int   g_count[N_NODES];
__device__ int   g_rowptr[N_NODES];
__device__ int   g_fill[N_NODES];
__device__ int   g_total;
__device__ int   g_csr_src[N_EDGES];
__device__ float g_csr_norm[N_EDGES];
__device__ float g_xw[(size_t)N_NODES * 128];   // x @ W scratch (also holds 50000x16 for layer 3)
__device__ float g_h[(size_t)N_NODES * 128];    // hidden activations

// ---------------- graph preprocessing ----------------
__global__ void init_nodes_kernel() {
    int i = blockIdx.x * blockDim.x + threadIdx.x;
    if (i == 0) g_total = 0;
    if (i < N_NODES) { g_deg[i] = 1.0f; g_count[i] = 0; }   // self-loop weight 1
}

__global__ void edge_deg_kernel(const int* __restrict__ dst, const float* __restrict__ ew) {
    int e = blockIdx.x * blockDim.x + threadIdx.x;
    if (e < N_EDGES) {
        int d = dst[e];
        atomicAdd(&g_deg[d], ew[e]);
        atomicAdd(&g_count[d], 1);
    }
}

// Segment allocation without a global scan: per-block local scan + one atomicAdd
// on a global cursor for the block's base. Also computes dinv (fused, saves a launch).
__global__ __launch_bounds__(256) void alloc_kernel() {
    int i = blockIdx.x * blockDim.x + threadIdx.x;
    int lane = threadIdx.x & 31, wid = threadIdx.x >> 5;
    int c = 0;
    if (i < N_NODES) {
        c = g_count[i];
        g_dinv[i] = rsqrtf(g_deg[i]);   // deg >= 1 always
    }
    // warp inclusive scan
    int p = c;
#pragma unroll
    for (int o = 1; o < 32; o <<= 1) {
        int v = __shfl_up_sync(0xffffffffu, p, o);
        if (lane >= o) p += v;
    }
    __shared__ int wsum[8];
    __shared__ int base;
    if (lane == 31) wsum[wid] = p;
    __syncthreads();
    if (threadIdx.x == 0) {
        int s = 0;
#pragma unroll
        for (int w = 0; w < 8; w++) { int t = wsum[w]; wsum[w] = s; s += t; }
        base = atomicAdd(&g_total, s);
    }
    __syncthreads();
    int off = base + wsum[wid] + (p - c);
    if (i < N_NODES) { g_rowptr[i] = off; g_fill[i] = off; }
}

__global__ void edge_scatter_kernel(const int* __restrict__ src, const int* __restrict__ dst,
                                    const float* __restrict__ ew) {
    int e = blockIdx.x * blockDim.x + threadIdx.x;
    if (e < N_EDGES) {
        int s = src[e], d = dst[e];
        int p = atomicAdd(&g_fill[d], 1);
        g_csr_src[p]  = s;
        g_csr_norm[p] = g_dinv[s] * ew[e] * g_dinv[d];
    }
}

// ---------------- tf32 tensor-core GEMM: [M,128] @ [128,128] -> [M,128] ----------------
// 256 thr / 8 warps, CTA tile 128x128, BK=32. Warp tile 32x64 (2x8 m16n8k8 tiles).
// Smem pads chosen for provably conflict-free fragment loads:
//   A pad 36: bank=(4*row+col)%32 distinct over (8 rows x 4 cols) lane pattern
//   W pad 136: bank=(8*tig+gid+n0)%32 distinct over (4 rows x 8 cols) lane pattern
__device__ __forceinline__ unsigned f2tf32(float f) {
    unsigned u;
    asm("cvt.rna.tf32.f32 %0, %1;" : "=r"(u) : "f"(f));
    return u;
}

__global__ __launch_bounds__(256) void gemm_tf32(const float* __restrict__ A,
                                                 const float* __restrict__ W,
                                                 float* __restrict__ C, int M) {
    const int K = 128, N = 128, BK = 32;
    const int APAD = 36, WPAD = 136;
    __shared__ unsigned as[128 * APAD];
    __shared__ unsigned ws[32 * WPAD];

    int tid = threadIdx.x;
    int wid = tid >> 5;
    int lane = tid & 31;
    int gid = lane >> 2;       // group 0..7
    int tig = lane & 3;        // 0..3
    int wr = wid & 3;          // warp row: 4 x 32 rows
    int wc = wid >> 2;         // warp col: 2 x 64 cols
    int rowBase = blockIdx.x * 128;

    float acc[2][8][4];
#pragma unroll
    for (int mt = 0; mt < 2; mt++)
#pragma unroll
        for (int nt = 0; nt < 8; nt++)
#pragma unroll
            for (int q = 0; q < 4; q++) acc[mt][nt][q] = 0.0f;

    int arow = tid >> 3;        // 0..31 (+32*rr)
    int acol = (tid & 7) * 4;
    int wrow = wid;             // 0..7 (+8*ww)
    int wcol = (tid & 31) * 4;

    for (int k0 = 0; k0 < K; k0 += BK) {
        // load A tile: 128 x 32
#pragma unroll
        for (int rr = 0; rr < 4; rr++) {
            int rl = arow + rr * 32;
            int row = rowBase + rl;
            float4 va = (row < M) ? *(const float4*)&A[(size_t)row * K + k0 + acol]
                                  : make_float4(0.f, 0.f, 0.f, 0.f);
            unsigned* p = &as[rl * APAD + acol];
            p[0] = f2tf32(va.x); p[1] = f2tf32(va.y);
            p[2] = f2tf32(va.z); p[3] = f2tf32(va.w);
        }
        // load W tile: 32 x 128
#pragma unroll
        for (int ww = 0; ww < 4; ww++) {
            int rl = wrow + ww * 8;
            float4 vw = *(const float4*)&W[(size_t)(k0 + rl) * N + wcol];
            unsigned* p = &ws[rl * WPAD + wcol];
            p[0] = f2tf32(vw.x); p[1] = f2tf32(vw.y);
            p[2] = f2tf32(vw.z); p[3] = f2tf32(vw.w);
        }
        __syncthreads();

#pragma unroll
        for (int kk = 0; kk < 4; kk++) {
            int k8 = kk * 8;
            unsigned afr[2][4];
#pragma unroll
            for (int mt = 0; mt < 2; mt++) {
                int m0 = wr * 32 + mt * 16;
                afr[mt][0] = as[(m0 + gid)     * APAD + k8 + tig];
                afr[mt][1] = as[(m0 + gid + 8) * APAD + k8 + tig];
                afr[mt][2] = as[(m0 + gid)     * APAD + k8 + tig + 4];
                afr[mt][3] = as[(m0 + gid + 8) * APAD + k8 + tig + 4];
            }
#pragma unroll
            for (int nt = 0; nt < 8; nt++) {
                int n0 = wc * 64 + nt * 8;
                unsigned b0 = ws[(k8 + tig)     * WPAD + n0 + gid];
                unsigned b1 = ws[(k8 + tig + 4) * WPAD + n0 + gid];
#pragma unroll
                for (int mt = 0; mt < 2; mt++) {
                    asm volatile(
                        "mma.sync.aligned.m16n8k8.row.col.f32.tf32.tf32.f32 "
                        "{%0,%1,%2,%3}, {%4,%5,%6,%7}, {%8,%9}, {%0,%1,%2,%3};"
                        : "+f"(acc[mt][nt][0]), "+f"(acc[mt][nt][1]),
                          "+f"(acc[mt][nt][2]), "+f"(acc[mt][nt][3])
                        : "r"(afr[mt][0]), "r"(afr[mt][1]),
                          "r"(afr[mt][2]), "r"(afr[mt][3]),
                          "r"(b0), "r"(b1));
                }
            }
        }
        __syncthreads();
    }

    // epilogue: c0,c1 -> (row, 2*tig), (row, 2*tig+1); c2,c3 -> row+8
#pragma unroll
    for (int mt = 0; mt < 2; mt++) {
        int r0 = rowBase + wr * 32 + mt * 16 + gid;
#pragma unroll
        for (int nt = 0; nt < 8; nt++) {
            int n0 = wc * 64 + nt * 8 + 2 * tig;
            if (r0 < M) {
                float2 o = {acc[mt][nt][0], acc[mt][nt][1]};
                *(float2*)&C[(size_t)r0 * N + n0] = o;
            }
            if (r0 + 8 < M) {
                float2 o = {acc[mt][nt][2], acc[mt][nt][3]};
                *(float2*)&C[(size_t)(r0 + 8) * N + n0] = o;
            }
        }
    }
}

// ---------------- SGEMM: [M,128] @ [128,16] -> [M,16] ----------------
__global__ __launch_bounds__(256) void gemm_f16k(const float* __restrict__ A,
                                                 const float* __restrict__ W,
                                                 float* __restrict__ C, int M) {
    const int K = 128, N = 16, BM = 256, BK = 16;
    __shared__ float xs[BK][BM];
    __shared__ float ws[BK][N];
    int tid = threadIdx.x;
    int ty = tid >> 2;
    int tx = tid & 3;
    int rowBase = blockIdx.x * BM;
    float acc[4][4];
#pragma unroll
    for (int i = 0; i < 4; i++)
#pragma unroll
        for (int j = 0; j < 4; j++) acc[i][j] = 0.0f;

    int lr = tid >> 2;
    int lk = (tid & 3) * 4;

    for (int k0 = 0; k0 < K; k0 += BK) {
#pragma unroll
        for (int rr = 0; rr < 4; rr++) {
            int rl = lr + rr * 64;
            int row = rowBase + rl;
            float4 va = (row < M) ? *(const float4*)&A[(size_t)row * K + k0 + lk]
                                  : make_float4(0.f, 0.f, 0.f, 0.f);
            xs[lk + 0][rl] = va.x; xs[lk + 1][rl] = va.y;
            xs[lk + 2][rl] = va.z; xs[lk + 3][rl] = va.w;
        }
        if (tid < 64) {
            int kk = tid >> 2;
            int nn = (tid & 3) * 4;
            *(float4*)&ws[kk][nn] = *(const float4*)&W[(size_t)(k0 + kk) * N + nn];
        }
        __syncthreads();
#pragma unroll
        for (int k = 0; k < BK; k++) {
            float4 a = *(const float4*)&xs[k][ty * 4];
            float4 b = *(const float4*)&ws[k][tx * 4];
            float av[4] = {a.x, a.y, a.z, a.w};
            float bv[4] = {b.x, b.y, b.z, b.w};
#pragma unroll
            for (int i = 0; i < 4; i++)
#pragma unroll
                for (int j = 0; j < 4; j++)
                    acc[i][j] = fmaf(av[i], bv[j], acc[i][j]);
        }
        __syncthreads();
    }
#pragma unroll
    for (int i = 0; i < 4; i++) {
        int r = rowBase + ty * 4 + i;
        if (r < M) {
            float4 o = {acc[i][0], acc[i][1], acc[i][2], acc[i][3]};
            *(float4*)&C[(size_t)r * N + tx * 4] = o;
        }
    }
}

// ---------------- aggregation: warp per node, 128 features ----------------
__global__ __launch_bounds__(256) void agg128_kernel(const float4* __restrict__ xw,
                                                     const float* __restrict__ bias,
                                                     float4* __restrict__ out, int do_relu) {
    int gw = (blockIdx.x * blockDim.x + threadIdx.x) >> 5;
    int lane = threadIdx.x & 31;
    if (gw >= N_NODES) return;
    int i = gw;
    float di = g_dinv[i];
    float s = di * di;                         // self-loop coeff d^-1
    float4 v = xw[(size_t)i * 32 + lane];
    float4 bb = ((const float4*)bias)[lane];
    float4 acc;
    acc.x = fmaf(v.x, s, bb.x); acc.y = fmaf(v.y, s, bb.y);
    acc.z = fmaf(v.z, s, bb.z); acc.w = fmaf(v.w, s, bb.w);

    int e0 = g_rowptr[i], e1 = e0 + g_count[i];
    for (int eb = e0; eb < e1; eb += 32) {
        int idx = eb + lane;
        int sj = 0; float wj = 0.0f;
        if (idx < e1) { sj = g_csr_src[idx]; wj = g_csr_norm[idx]; }
        int cnt = min(32, e1 - eb);
        for (int j = 0; j < cnt; j++) {
            int   sk = __shfl_sync(0xffffffffu, sj, j);
            float wk = __shfl_sync(0xffffffffu, wj, j);
            float4 u = __ldg(&xw[(size_t)sk * 32 + lane]);
            acc.x = fmaf(wk, u.x, acc.x);
            acc.y = fmaf(wk, u.y, acc.y);
            acc.z = fmaf(wk, u.z, acc.z);
            acc.w = fmaf(wk, u.w, acc.w);
        }
    }
    if (do_relu) {
        acc.x = fmaxf(acc.x, 0.f); acc.y = fmaxf(acc.y, 0.f);
        acc.z = fmaxf(acc.z, 0.f); acc.w = fmaxf(acc.w, 0.f);
    }
    out[(size_t)i * 32 + lane] = acc;
}

// ---------------- aggregation + log_softmax: warp per node, 16 features ----------------
__global__ __launch_bounds__(256) void agg16_lsm_kernel(const float* __restrict__ xw,
                                                        const float* __restrict__ bias,
                                                        float* __restrict__ out) {
    int gw = (blockIdx.x * blockDim.x + threadIdx.x) >> 5;
    int lane = threadIdx.x & 31;
    if (gw >= N_NODES) return;
    int i = gw;
    float di = g_dinv[i];
    float s = di * di;
    float acc = 0.0f;
    if (lane < 16) acc = fmaf(xw[(size_t)i * 16 + lane], s, bias[lane]);

    int e0 = g_rowptr[i], e1 = e0 + g_count[i];
    for (int eb = e0; eb < e1; eb += 32) {
        int idx = eb + lane;
        int sj = 0; float wj = 0.0f;
        if (idx < e1) { sj = g_csr_src[idx]; wj = g_csr_norm[idx]; }
        int cnt = min(32, e1 - eb);
        for (int j = 0; j < cnt; j++) {
            int   sk = __shfl_sync(0xffffffffu, sj, j);
            float wk = __shfl_sync(0xffffffffu, wj, j);
            if (lane < 16)
                acc = fmaf(wk, __ldg(&xw[(size_t)sk * 16 + lane]), acc);
        }
    }
    float v = (lane < 16) ? acc : -INFINITY;
    float m = v;
#pragma unroll
    for (int o = 8; o > 0; o >>= 1) m = fmaxf(m, __shfl_xor_sync(0xffffffffu, m, o));
    float ee = (lane < 16) ? expf(acc - m) : 0.0f;
    float ss = ee;
#pragma unroll
    for (int o = 8; o > 0; o >>= 1) ss += __shfl_xor_sync(0xffffffffu, ss, o);
    if (lane < 16) out[(size_t)i * 16 + lane] = acc - m - logf(ss);
}

// ---------------- launch ----------------
extern "C" void kernel_launch(void* const* d_in, const int* in_sizes, int n_in,
                              void* d_out, int out_size) {
    const float* x    = (const float*)d_in[0];
    const int*   esrc = (const int*)d_in[1];
    const int*   edst = (const int*)d_in[2];
    const float* ew   = (const float*)d_in[3];
    const float* W1   = (const float*)d_in[4];
    const float* b1   = (const float*)d_in[5];
    const float* W2   = (const float*)d_in[6];
    const float* b2   = (const float*)d_in[7];
    const float* W3   = (const float*)d_in[8];
    const float* b3   = (const float*)d_in[9];
    float* out = (float*)d_out;

    float *p_xw = nullptr, *p_h = nullptr;
    cudaGetSymbolAddress((void**)&p_xw, g_xw);
    cudaGetSymbolAddress((void**)&p_h,  g_h);

    const int NB_NODE = (N_NODES + 255) / 256;       // 196
    const int NB_EDGE = (N_EDGES + 255) / 256;       // 1954
    const int NB_WARP = (N_NODES * 32 + 255) / 256;  // 6250 (warp per node)
    const int NB_G128 = (N_NODES + 127) / 128;       // 391
    const int NB_G16  = (N_NODES + 255) / 256;       // 196

    // graph preprocessing (rebuilt every call; deterministic work)
    init_nodes_kernel<<<NB_NODE, 256>>>();
    edge_deg_kernel<<<NB_EDGE, 256>>>(edst, ew);
    alloc_kernel<<<NB_NODE, 256>>>();
    edge_scatter_kernel<<<NB_EDGE, 256>>>(esrc, edst, ew);

    // layer 1: h = relu(agg(x @ W1) + b1)
    gemm_tf32<<<NB_G128, 256>>>(x, W1, p_xw, N_NODES);
    agg128_kernel<<<NB_WARP, 256>>>((const float4*)p_xw, b1, (float4*)p_h, 1);

    // layer 2: h = relu(agg(h @ W2) + b2)
    gemm_tf32<<<NB_G128, 256>>>(p_h, W2, p_xw, N_NODES);
    agg128_kernel<<<NB_WARP, 256>>>((const float4*)p_xw, b2, (float4*)p_h, 1);

    // layer 3: out = log_softmax(agg(h @ W3) + b3)
    gemm_f16k<<<NB_G16, 256>>>(p_h, W3, p_xw, N_NODES);
    agg16_lsm_kernel<<<NB_WARP, 256>>>(p_xw, b3, out);
}

// round 14
// speedup vs baseline: 1.5359x; 1.0564x over previous
#include <cuda_runtime.h>
#include <cuda_fp16.h>
#include <math.h>

#define N_NODES 50000
#define N_EDGES 500000
#define NFEAT   128
#define NHID    128
#define NOUT    16

// ---------------- device scratch (static allocation is allowed) ----------------
__device__ float  g_deg[N_NODES];
__device__ float  g_dinv[N_NODES];
__device__ int    g_count[N_NODES];
__device__ int    g_rowptr[N_NODES];
__device__ int    g_fill[N_NODES];
__device__ int    g_total;
__device__ int    g_csr_src[N_EDGES];
__device__ float  g_csr_w[N_EDGES];             // raw edge weight (dinv folded elsewhere)
__device__ __half g_xw16[(size_t)N_NODES * 128]; // dinv-scaled x@W, fp16 (gather payload)
__device__ float  g_xw3[(size_t)N_NODES * 16];   // layer-3 dinv-scaled h@W3, fp32
__device__ float  g_h[(size_t)N_NODES * 128];    // hidden activations, fp32

// ---------------- graph preprocessing ----------------
__global__ void init_nodes_kernel() {
    int i = blockIdx.x * blockDim.x + threadIdx.x;
    if (i == 0) g_total = 0;
    if (i < N_NODES) { g_deg[i] = 1.0f; g_count[i] = 0; }   // self-loop weight 1
}

__global__ void edge_deg_kernel(const int* __restrict__ dst, const float* __restrict__ ew) {
    int e = blockIdx.x * blockDim.x + threadIdx.x;
    if (e < N_EDGES) {
        int d = dst[e];
        atomicAdd(&g_deg[d], ew[e]);
        atomicAdd(&g_count[d], 1);
    }
}

// Segment allocation without a global scan: per-block local scan + one atomicAdd
// on a global cursor for the block's base. Also computes dinv (fused).
__global__ __launch_bounds__(256) void alloc_kernel() {
    int i = blockIdx.x * blockDim.x + threadIdx.x;
    int lane = threadIdx.x & 31, wid = threadIdx.x >> 5;
    int c = 0;
    if (i < N_NODES) {
        c = g_count[i];
        g_dinv[i] = rsqrtf(g_deg[i]);   // deg >= 1 always
    }
    int p = c;
#pragma unroll
    for (int o = 1; o < 32; o <<= 1) {
        int v = __shfl_up_sync(0xffffffffu, p, o);
        if (lane >= o) p += v;
    }
    __shared__ int wsum[8];
    __shared__ int base;
    if (lane == 31) wsum[wid] = p;
    __syncthreads();
    if (threadIdx.x == 0) {
        int s = 0;
#pragma unroll
        for (int w = 0; w < 8; w++) { int t = wsum[w]; wsum[w] = s; s += t; }
        base = atomicAdd(&g_total, s);
    }
    __syncthreads();
    int off = base + wsum[wid] + (p - c);
    if (i < N_NODES) { g_rowptr[i] = off; g_fill[i] = off; }
}

// No dinv gathers here anymore: csr weight is the raw edge weight.
__global__ void edge_scatter_kernel(const int* __restrict__ src, const int* __restrict__ dst,
                                    const float* __restrict__ ew) {
    int e = blockIdx.x * blockDim.x + threadIdx.x;
    if (e < N_EDGES) {
        int d = dst[e];
        int p = atomicAdd(&g_fill[d], 1);
        g_csr_src[p] = src[e];
        g_csr_w[p]   = ew[e];
    }
}

// ---------------- tf32 tensor-core GEMM: [M,128] @ [128,128] -> dinv-scaled fp16 ----------------
__device__ __forceinline__ unsigned f2tf32(float f) {
    unsigned u;
    asm("cvt.rna.tf32.f32 %0, %1;" : "=r"(u) : "f"(f));
    return u;
}

__global__ __launch_bounds__(256) void gemm_tf32(const float* __restrict__ A,
                                                 const float* __restrict__ W,
                                                 __half* __restrict__ C, int M) {
    const int K = 128, N = 128, BK = 32;
    const int APAD = 36, WPAD = 136;
    __shared__ unsigned as[128 * APAD];
    __shared__ unsigned ws[32 * WPAD];

    int tid = threadIdx.x;
    int wid = tid >> 5;
    int lane = tid & 31;
    int gid = lane >> 2;
    int tig = lane & 3;
    int wr = wid & 3;
    int wc = wid >> 2;
    int rowBase = blockIdx.x * 128;

    float acc[2][8][4];
#pragma unroll
    for (int mt = 0; mt < 2; mt++)
#pragma unroll
        for (int nt = 0; nt < 8; nt++)
#pragma unroll
            for (int q = 0; q < 4; q++) acc[mt][nt][q] = 0.0f;

    int arow = tid >> 3;
    int acol = (tid & 7) * 4;
    int wrow = wid;
    int wcol = (tid & 31) * 4;

    for (int k0 = 0; k0 < K; k0 += BK) {
#pragma unroll
        for (int rr = 0; rr < 4; rr++) {
            int rl = arow + rr * 32;
            int row = rowBase + rl;
            float4 va = (row < M) ? *(const float4*)&A[(size_t)row * K + k0 + acol]
                                  : make_float4(0.f, 0.f, 0.f, 0.f);
            unsigned* p = &as[rl * APAD + acol];
            p[0] = f2tf32(va.x); p[1] = f2tf32(va.y);
            p[2] = f2tf32(va.z); p[3] = f2tf32(va.w);
        }
#pragma unroll
        for (int ww = 0; ww < 4; ww++) {
            int rl = wrow + ww * 8;
            float4 vw = *(const float4*)&W[(size_t)(k0 + rl) * N + wcol];
            unsigned* p = &ws[rl * WPAD + wcol];
            p[0] = f2tf32(vw.x); p[1] = f2tf32(vw.y);
            p[2] = f2tf32(vw.z); p[3] = f2tf32(vw.w);
        }
        __syncthreads();

#pragma unroll
        for (int kk = 0; kk < 4; kk++) {
            int k8 = kk * 8;
            unsigned afr[2][4];
#pragma unroll
            for (int mt = 0; mt < 2; mt++) {
                int m0 = wr * 32 + mt * 16;
                afr[mt][0] = as[(m0 + gid)     * APAD + k8 + tig];
                afr[mt][1] = as[(m0 + gid + 8) * APAD + k8 + tig];
                afr[mt][2] = as[(m0 + gid)     * APAD + k8 + tig + 4];
                afr[mt][3] = as[(m0 + gid + 8) * APAD + k8 + tig + 4];
            }
#pragma unroll
            for (int nt = 0; nt < 8; nt++) {
                int n0 = wc * 64 + nt * 8;
                unsigned b0 = ws[(k8 + tig)     * WPAD + n0 + gid];
                unsigned b1 = ws[(k8 + tig + 4) * WPAD + n0 + gid];
#pragma unroll
                for (int mt = 0; mt < 2; mt++) {
                    asm volatile(
                        "mma.sync.aligned.m16n8k8.row.col.f32.tf32.tf32.f32 "
                        "{%0,%1,%2,%3}, {%4,%5,%6,%7}, {%8,%9}, {%0,%1,%2,%3};"
                        : "+f"(acc[mt][nt][0]), "+f"(acc[mt][nt][1]),
                          "+f"(acc[mt][nt][2]), "+f"(acc[mt][nt][3])
                        : "r"(afr[mt][0]), "r"(afr[mt][1]),
                          "r"(afr[mt][2]), "r"(afr[mt][3]),
                          "r"(b0), "r"(b1));
                }
            }
        }
        __syncthreads();
    }

    // epilogue: scale row r by dinv[r] (fold one normalization factor), write fp16
#pragma unroll
    for (int mt = 0; mt < 2; mt++) {
        int r0 = rowBase + wr * 32 + mt * 16 + gid;
        float s0 = (r0 < M)     ? g_dinv[r0]     : 0.0f;
        float s1 = (r0 + 8 < M) ? g_dinv[r0 + 8] : 0.0f;
#pragma unroll
        for (int nt = 0; nt < 8; nt++) {
            int n0 = wc * 64 + nt * 8 + 2 * tig;
            if (r0 < M) {
                __half2 o = __floats2half2_rn(acc[mt][nt][0] * s0, acc[mt][nt][1] * s0);
                *(__half2*)&C[(size_t)r0 * N + n0] = o;
            }
            if (r0 + 8 < M) {
                __half2 o = __floats2half2_rn(acc[mt][nt][2] * s1, acc[mt][nt][3] * s1);
                *(__half2*)&C[(size_t)(r0 + 8) * N + n0] = o;
            }
        }
    }
}

// ---------------- SGEMM: [M,128] @ [128,16] -> dinv-scaled fp32 ----------------
__global__ __launch_bounds__(256) void gemm_f16k(const float* __restrict__ A,
                                                 const float* __restrict__ W,
                                                 float* __restrict__ C, int M) {
    const int K = 128, N = 16, BM = 256, BK = 16;
    __shared__ float xs[BK][BM];
    __shared__ float ws[BK][N];
    int tid = threadIdx.x;
    int ty = tid >> 2;
    int tx = tid & 3;
    int rowBase = blockIdx.x * BM;
    float acc[4][4];
#pragma unroll
    for (int i = 0; i < 4; i++)
#pragma unroll
        for (int j = 0; j < 4; j++) acc[i][j] = 0.0f;

    int lr = tid >> 2;
    int lk = (tid & 3) * 4;

    for (int k0 = 0; k0 < K; k0 += BK) {
#pragma unroll
        for (int rr = 0; rr < 4; rr++) {
            int rl = lr + rr * 64;
            int row = rowBase + rl;
            float4 va = (row < M) ? *(const float4*)&A[(size_t)row * K + k0 + lk]
                                  : make_float4(0.f, 0.f, 0.f, 0.f);
            xs[lk + 0][rl] = va.x; xs[lk + 1][rl] = va.y;
            xs[lk + 2][rl] = va.z; xs[lk + 3][rl] = va.w;
        }
        if (tid < 64) {
            int kk = tid >> 2;
            int nn = (tid & 3) * 4;
            *(float4*)&ws[kk][nn] = *(const float4*)&W[(size_t)(k0 + kk) * N + nn];
        }
        __syncthreads();
#pragma unroll
        for (int k = 0; k < BK; k++) {
            float4 a = *(const float4*)&xs[k][ty * 4];
            float4 b = *(const float4*)&ws[k][tx * 4];
            float av[4] = {a.x, a.y, a.z, a.w};
            float bv[4] = {b.x, b.y, b.z, b.w};
#pragma unroll
            for (int i = 0; i < 4; i++)
#pragma unroll
                for (int j = 0; j < 4; j++)
                    acc[i][j] = fmaf(av[i], bv[j], acc[i][j]);
        }
        __syncthreads();
    }
#pragma unroll
    for (int i = 0; i < 4; i++) {
        int r = rowBase + ty * 4 + i;
        if (r < M) {
            float s = g_dinv[r];
            float4 o = {acc[i][0] * s, acc[i][1] * s, acc[i][2] * s, acc[i][3] * s};
            *(float4*)&C[(size_t)r * N + tx * 4] = o;
        }
    }
}

// ---------------- aggregation: warp per node, 128 features, fp16 gather ----------------
// acc_i = dinv_i * (xw'_i + sum_e w_e * xw'_src) + b   where xw' = dinv .* (x@W)
__global__ __launch_bounds__(256) void agg128_kernel(const __half* __restrict__ xw,
                                                     const float* __restrict__ bias,
                                                     float4* __restrict__ out) {
    int gw = (blockIdx.x * blockDim.x + threadIdx.x) >> 5;
    int lane = threadIdx.x & 31;
    if (gw >= N_NODES) return;
    int i = gw;
    const uint2* xwv = (const uint2*)xw;   // 4 halves per uint2; row stride = 32

    uint2 rv = __ldg(&xwv[(size_t)i * 32 + lane]);
    float2 f0 = __half22float2(*(__half2*)&rv.x);
    float2 f1 = __half22float2(*(__half2*)&rv.y);
    float4 acc = {f0.x, f0.y, f1.x, f1.y};   // self term (already dinv_src-scaled)

    int e0 = g_rowptr[i], e1 = e0 + g_count[i];
    for (int eb = e0; eb < e1; eb += 32) {
        int idx = eb + lane;
        int sj = 0; float wj = 0.0f;
        if (idx < e1) { sj = g_csr_src[idx]; wj = g_csr_w[idx]; }
        int cnt = min(32, e1 - eb);
        for (int j = 0; j < cnt; j++) {
            int   sk = __shfl_sync(0xffffffffu, sj, j);
            float wk = __shfl_sync(0xffffffffu, wj, j);
            uint2 uv = __ldg(&xwv[(size_t)sk * 32 + lane]);
            float2 u0 = __half22float2(*(__half2*)&uv.x);
            float2 u1 = __half22float2(*(__half2*)&uv.y);
            acc.x = fmaf(wk, u0.x, acc.x);
            acc.y = fmaf(wk, u0.y, acc.y);
            acc.z = fmaf(wk, u1.x, acc.z);
            acc.w = fmaf(wk, u1.y, acc.w);
        }
    }
    float di = g_dinv[i];
    float4 bb = ((const float4*)bias)[lane];
    acc.x = fmaxf(fmaf(acc.x, di, bb.x), 0.f);
    acc.y = fmaxf(fmaf(acc.y, di, bb.y), 0.f);
    acc.z = fmaxf(fmaf(acc.z, di, bb.z), 0.f);
    acc.w = fmaxf(fmaf(acc.w, di, bb.w), 0.f);
    out[(size_t)i * 32 + lane] = acc;
}

// ---------------- aggregation + log_softmax: warp per node, 16 features ----------------
__global__ __launch_bounds__(256) void agg16_lsm_kernel(const float* __restrict__ xw,
                                                        const float* __restrict__ bias,
                                                        float* __restrict__ out) {
    int gw = (blockIdx.x * blockDim.x + threadIdx.x) >> 5;
    int lane = threadIdx.x & 31;
    if (gw >= N_NODES) return;
    int i = gw;
    float acc = (lane < 16) ? xw[(size_t)i * 16 + lane] : 0.0f;   // self term

    int e0 = g_rowptr[i], e1 = e0 + g_count[i];
    for (int eb = e0; eb < e1; eb += 32) {
        int idx = eb + lane;
        int sj = 0; float wj = 0.0f;
        if (idx < e1) { sj = g_csr_src[idx]; wj = g_csr_w[idx]; }
        int cnt = min(32, e1 - eb);
        for (int j = 0; j < cnt; j++) {
            int   sk = __shfl_sync(0xffffffffu, sj, j);
            float wk = __shfl_sync(0xffffffffu, wj, j);
            if (lane < 16)
                acc = fmaf(wk, __ldg(&xw[(size_t)sk * 16 + lane]), acc);
        }
    }
    float di = g_dinv[i];
    if (lane < 16) acc = fmaf(acc, di, bias[lane]);

    float v = (lane < 16) ? acc : -INFINITY;
    float m = v;
#pragma unroll
    for (int o = 8; o > 0; o >>= 1) m = fmaxf(m, __shfl_xor_sync(0xffffffffu, m, o));
    float ee = (lane < 16) ? expf(acc - m) : 0.0f;
    float ss = ee;
#pragma unroll
    for (int o = 8; o > 0; o >>= 1) ss += __shfl_xor_sync(0xffffffffu, ss, o);
    if (lane < 16) out[(size_t)i * 16 + lane] = acc - m - logf(ss);
}

// ---------------- launch ----------------
extern "C" void kernel_launch(void* const* d_in, const int* in_sizes, int n_in,
                              void* d_out, int out_size) {
    const float* x    = (const float*)d_in[0];
    const int*   esrc = (const int*)d_in[1];
    const int*   edst = (const int*)d_in[2];
    const float* ew   = (const float*)d_in[3];
    const float* W1   = (const float*)d_in[4];
    const float* b1   = (const float*)d_in[5];
    const float* W2   = (const float*)d_in[6];
    const float* b2   = (const float*)d_in[7];
    const float* W3   = (const float*)d_in[8];
    const float* b3   = (const float*)d_in[9];
    float* out = (float*)d_out;

    __half* p_xw16 = nullptr;
    float *p_xw3 = nullptr, *p_h = nullptr;
    cudaGetSymbolAddress((void**)&p_xw16, g_xw16);
    cudaGetSymbolAddress((void**)&p_xw3,  g_xw3);
    cudaGetSymbolAddress((void**)&p_h,    g_h);

    const int NB_NODE = (N_NODES + 255) / 256;       // 196
    const int NB_EDGE = (N_EDGES + 255) / 256;       // 1954
    const int NB_WARP = (N_NODES * 32 + 255) / 256;  // 6250 (warp per node)
    const int NB_G128 = (N_NODES + 127) / 128;       // 391
    const int NB_G16  = (N_NODES + 255) / 256;       // 196

    // graph preprocessing (rebuilt every call; deterministic work)
    init_nodes_kernel<<<NB_NODE, 256>>>();
    edge_deg_kernel<<<NB_EDGE, 256>>>(edst, ew);
    alloc_kernel<<<NB_NODE, 256>>>();
    edge_scatter_kernel<<<NB_EDGE, 256>>>(esrc, edst, ew);

    // layer 1: h = relu(agg(x @ W1) + b1)
    gemm_tf32<<<NB_G128, 256>>>(x, W1, p_xw16, N_NODES);
    agg128_kernel<<<NB_WARP, 256>>>(p_xw16, b1, (float4*)p_h);

    // layer 2: h = relu(agg(h @ W2) + b2)
    gemm_tf32<<<NB_G128, 256>>>(p_h, W2, p_xw16, N_NODES);
    agg128_kernel<<<NB_WARP, 256>>>(p_xw16, b2, (float4*)p_h);

    // layer 3: out = log_softmax(agg(h @ W3) + b3)
    gemm_f16k<<<NB_G16, 256>>>(p_h, W3, p_xw3, N_NODES);
    agg16_lsm_kernel<<<NB_WARP, 256>>>(p_xw3, b3, out);
}

// round 15
// speedup vs baseline: 1.6607x; 1.0813x over previous
#include <cuda_runtime.h>
#include <cuda_fp16.h>
#include <math.h>

#define N_NODES 50000
#define N_EDGES 500000
#define NFEAT   128
#define NHID    128
#define NOUT    16

// ---------------- device scratch (static allocation is allowed) ----------------
__device__ float  g_deg[N_NODES];
__device__ float  g_dinv[N_NODES];
__device__ int    g_count[N_NODES];
__device__ int    g_rowptr[N_NODES];
__device__ int    g_fill[N_NODES];
__device__ int    g_total;
__device__ int2   g_csr[N_EDGES];                // packed (src, ew bits) — 1 sector per edge
__device__ __half g_xw16[(size_t)N_NODES * 128]; // dinv-scaled x@W, fp16 (gather payload)
__device__ float  g_xw3[(size_t)N_NODES * 16];   // layer-3 dinv-scaled h@W3, fp32
__device__ float  g_h[(size_t)N_NODES * 128];    // hidden activations, fp32

// ---------------- graph preprocessing ----------------
__global__ void init_nodes_kernel() {
    int i = blockIdx.x * blockDim.x + threadIdx.x;
    if (i == 0) g_total = 0;
    if (i < N_NODES) { g_deg[i] = 1.0f; g_count[i] = 0; }   // self-loop weight 1
}

__global__ void edge_deg_kernel(const int* __restrict__ dst, const float* __restrict__ ew) {
    int e = blockIdx.x * blockDim.x + threadIdx.x;
    if (e < N_EDGES) {
        int d = dst[e];
        atomicAdd(&g_deg[d], ew[e]);
        atomicAdd(&g_count[d], 1);
    }
}

// Segment allocation without a global scan: per-block local scan + one atomicAdd
// on a global cursor for the block's base. Also computes dinv (fused).
__global__ __launch_bounds__(256) void alloc_kernel() {
    int i = blockIdx.x * blockDim.x + threadIdx.x;
    int lane = threadIdx.x & 31, wid = threadIdx.x >> 5;
    int c = 0;
    if (i < N_NODES) {
        c = g_count[i];
        g_dinv[i] = rsqrtf(g_deg[i]);   // deg >= 1 always
    }
    int p = c;
#pragma unroll
    for (int o = 1; o < 32; o <<= 1) {
        int v = __shfl_up_sync(0xffffffffu, p, o);
        if (lane >= o) p += v;
    }
    __shared__ int wsum[8];
    __shared__ int base;
    if (lane == 31) wsum[wid] = p;
    __syncthreads();
    if (threadIdx.x == 0) {
        int s = 0;
#pragma unroll
        for (int w = 0; w < 8; w++) { int t = wsum[w]; wsum[w] = s; s += t; }
        base = atomicAdd(&g_total, s);
    }
    __syncthreads();
    int off = base + wsum[wid] + (p - c);
    if (i < N_NODES) { g_rowptr[i] = off; g_fill[i] = off; }
}

__global__ void edge_scatter_kernel(const int* __restrict__ src, const int* __restrict__ dst,
                                    const float* __restrict__ ew) {
    int e = blockIdx.x * blockDim.x + threadIdx.x;
    if (e < N_EDGES) {
        int d = dst[e];
        int p = atomicAdd(&g_fill[d], 1);
        g_csr[p] = make_int2(src[e], __float_as_int(ew[e]));
    }
}

// ---------------- tf32 tensor-core GEMM: [M,128] @ [128,128] -> dinv-scaled fp16 ----------------
__device__ __forceinline__ unsigned f2tf32(float f) {
    unsigned u;
    asm("cvt.rna.tf32.f32 %0, %1;" : "=r"(u) : "f"(f));
    return u;
}

__global__ __launch_bounds__(256) void gemm_tf32(const float* __restrict__ A,
                                                 const float* __restrict__ W,
                                                 __half* __restrict__ C, int M) {
    const int K = 128, N = 128, BK = 32;
    const int APAD = 36, WPAD = 136;
    __shared__ unsigned as[128 * APAD];
    __shared__ unsigned ws[32 * WPAD];

    int tid = threadIdx.x;
    int wid = tid >> 5;
    int lane = tid & 31;
    int gid = lane >> 2;
    int tig = lane & 3;
    int wr = wid & 3;
    int wc = wid >> 2;
    int rowBase = blockIdx.x * 128;

    float acc[2][8][4];
#pragma unroll
    for (int mt = 0; mt < 2; mt++)
#pragma unroll
        for (int nt = 0; nt < 8; nt++)
#pragma unroll
            for (int q = 0; q < 4; q++) acc[mt][nt][q] = 0.0f;

    int arow = tid >> 3;
    int acol = (tid & 7) * 4;
    int wrow = wid;
    int wcol = (tid & 31) * 4;

    for (int k0 = 0; k0 < K; k0 += BK) {
#pragma unroll
        for (int rr = 0; rr < 4; rr++) {
            int rl = arow + rr * 32;
            int row = rowBase + rl;
            float4 va = (row < M) ? *(const float4*)&A[(size_t)row * K + k0 + acol]
                                  : make_float4(0.f, 0.f, 0.f, 0.f);
            unsigned* p = &as[rl * APAD + acol];
            p[0] = f2tf32(va.x); p[1] = f2tf32(va.y);
            p[2] = f2tf32(va.z); p[3] = f2tf32(va.w);
        }
#pragma unroll
        for (int ww = 0; ww < 4; ww++) {
            int rl = wrow + ww * 8;
            float4 vw = *(const float4*)&W[(size_t)(k0 + rl) * N + wcol];
            unsigned* p = &ws[rl * WPAD + wcol];
            p[0] = f2tf32(vw.x); p[1] = f2tf32(vw.y);
            p[2] = f2tf32(vw.z); p[3] = f2tf32(vw.w);
        }
        __syncthreads();

#pragma unroll
        for (int kk = 0; kk < 4; kk++) {
            int k8 = kk * 8;
            unsigned afr[2][4];
#pragma unroll
            for (int mt = 0; mt < 2; mt++) {
                int m0 = wr * 32 + mt * 16;
                afr[mt][0] = as[(m0 + gid)     * APAD + k8 + tig];
                afr[mt][1] = as[(m0 + gid + 8) * APAD + k8 + tig];
                afr[mt][2] = as[(m0 + gid)     * APAD + k8 + tig + 4];
                afr[mt][3] = as[(m0 + gid + 8) * APAD + k8 + tig + 4];
            }
#pragma unroll
            for (int nt = 0; nt < 8; nt++) {
                int n0 = wc * 64 + nt * 8;
                unsigned b0 = ws[(k8 + tig)     * WPAD + n0 + gid];
                unsigned b1 = ws[(k8 + tig + 4) * WPAD + n0 + gid];
#pragma unroll
                for (int mt = 0; mt < 2; mt++) {
                    asm volatile(
                        "mma.sync.aligned.m16n8k8.row.col.f32.tf32.tf32.f32 "
                        "{%0,%1,%2,%3}, {%4,%5,%6,%7}, {%8,%9}, {%0,%1,%2,%3};"
                        : "+f"(acc[mt][nt][0]), "+f"(acc[mt][nt][1]),
                          "+f"(acc[mt][nt][2]), "+f"(acc[mt][nt][3])
                        : "r"(afr[mt][0]), "r"(afr[mt][1]),
                          "r"(afr[mt][2]), "r"(afr[mt][3]),
                          "r"(b0), "r"(b1));
                }
            }
        }
        __syncthreads();
    }

    // epilogue: scale row r by dinv[r] (fold src normalization), write fp16
#pragma unroll
    for (int mt = 0; mt < 2; mt++) {
        int r0 = rowBase + wr * 32 + mt * 16 + gid;
        float s0 = (r0 < M)     ? g_dinv[r0]     : 0.0f;
        float s1 = (r0 + 8 < M) ? g_dinv[r0 + 8] : 0.0f;
#pragma unroll
        for (int nt = 0; nt < 8; nt++) {
            int n0 = wc * 64 + nt * 8 + 2 * tig;
            if (r0 < M) {
                __half2 o = __floats2half2_rn(acc[mt][nt][0] * s0, acc[mt][nt][1] * s0);
                *(__half2*)&C[(size_t)r0 * N + n0] = o;
            }
            if (r0 + 8 < M) {
                __half2 o = __floats2half2_rn(acc[mt][nt][2] * s1, acc[mt][nt][3] * s1);
                *(__half2*)&C[(size_t)(r0 + 8) * N + n0] = o;
            }
        }
    }
}

// ---------------- SGEMM: [M,128] @ [128,16] -> dinv-scaled fp32 ----------------
__global__ __launch_bounds__(256) void gemm_f16k(const float* __restrict__ A,
                                                 const float* __restrict__ W,
                                                 float* __restrict__ C, int M) {
    const int K = 128, N = 16, BM = 256, BK = 16;
    __shared__ float xs[BK][BM];
    __shared__ float ws[BK][N];
    int tid = threadIdx.x;
    int ty = tid >> 2;
    int tx = tid & 3;
    int rowBase = blockIdx.x * BM;
    float acc[4][4];
#pragma unroll
    for (int i = 0; i < 4; i++)
#pragma unroll
        for (int j = 0; j < 4; j++) acc[i][j] = 0.0f;

    int lr = tid >> 2;
    int lk = (tid & 3) * 4;

    for (int k0 = 0; k0 < K; k0 += BK) {
#pragma unroll
        for (int rr = 0; rr < 4; rr++) {
            int rl = lr + rr * 64;
            int row = rowBase + rl;
            float4 va = (row < M) ? *(const float4*)&A[(size_t)row * K + k0 + lk]
                                  : make_float4(0.f, 0.f, 0.f, 0.f);
            xs[lk + 0][rl] = va.x; xs[lk + 1][rl] = va.y;
            xs[lk + 2][rl] = va.z; xs[lk + 3][rl] = va.w;
        }
        if (tid < 64) {
            int kk = tid >> 2;
            int nn = (tid & 3) * 4;
            *(float4*)&ws[kk][nn] = *(const float4*)&W[(size_t)(k0 + kk) * N + nn];
        }
        __syncthreads();
#pragma unroll
        for (int k = 0; k < BK; k++) {
            float4 a = *(const float4*)&xs[k][ty * 4];
            float4 b = *(const float4*)&ws[k][tx * 4];
            float av[4] = {a.x, a.y, a.z, a.w};
            float bv[4] = {b.x, b.y, b.z, b.w};
#pragma unroll
            for (int i = 0; i < 4; i++)
#pragma unroll
                for (int j = 0; j < 4; j++)
                    acc[i][j] = fmaf(av[i], bv[j], acc[i][j]);
        }
        __syncthreads();
    }
#pragma unroll
    for (int i = 0; i < 4; i++) {
        int r = rowBase + ty * 4 + i;
        if (r < M) {
            float s = g_dinv[r];
            float4 o = {acc[i][0] * s, acc[i][1] * s, acc[i][2] * s, acc[i][3] * s};
            *(float4*)&C[(size_t)r * N + tx * 4] = o;
        }
    }
}

// ---------------- aggregation: warp per node, 128 features, fp16 gather ----------------
// out_i = relu(dinv_i * (xw'_i + sum_e w_e * xw'_src) + b)  where xw' = dinv .* (x@W)
__global__ __launch_bounds__(256) void agg128_kernel(const __half* __restrict__ xw,
                                                     const float* __restrict__ bias,
                                                     float4* __restrict__ out) {
    int gw = (blockIdx.x * blockDim.x + threadIdx.x) >> 5;
    int lane = threadIdx.x & 31;
    if (gw >= N_NODES) return;
    int i = gw;
    const uint2* xwv = (const uint2*)xw;   // 4 halves per uint2; row stride = 32

    uint2 rv = __ldg(&xwv[(size_t)i * 32 + lane]);
    float2 f0 = __half22float2(*(__half2*)&rv.x);
    float2 f1 = __half22float2(*(__half2*)&rv.y);
    float4 acc = {f0.x, f0.y, f1.x, f1.y};   // self term (already dinv_src-scaled)

    int e0 = g_rowptr[i], e1 = e0 + g_count[i];
    for (int eb = e0; eb < e1; eb += 32) {
        int idx = eb + lane;
        int2 c = make_int2(0, 0);
        if (idx < e1) c = __ldg(&g_csr[idx]);
        int cnt = min(32, e1 - eb);
        for (int j = 0; j < cnt; j++) {
            int   sk = __shfl_sync(0xffffffffu, c.x, j);
            float wk = __int_as_float(__shfl_sync(0xffffffffu, c.y, j));
            uint2 uv = __ldg(&xwv[(size_t)sk * 32 + lane]);
            float2 u0 = __half22float2(*(__half2*)&uv.x);
            float2 u1 = __half22float2(*(__half2*)&uv.y);
            acc.x = fmaf(wk, u0.x, acc.x);
            acc.y = fmaf(wk, u0.y, acc.y);
            acc.z = fmaf(wk, u1.x, acc.z);
            acc.w = fmaf(wk, u1.y, acc.w);
        }
    }
    float di = g_dinv[i];
    float4 bb = ((const float4*)bias)[lane];
    acc.x = fmaxf(fmaf(acc.x, di, bb.x), 0.f);
    acc.y = fmaxf(fmaf(acc.y, di, bb.y), 0.f);
    acc.z = fmaxf(fmaf(acc.z, di, bb.z), 0.f);
    acc.w = fmaxf(fmaf(acc.w, di, bb.w), 0.f);
    out[(size_t)i * 32 + lane] = acc;
}

// ---------------- aggregation + log_softmax: HALF-warp per node, 16 features ----------------
__global__ __launch_bounds__(256) void agg16_lsm_kernel(const float* __restrict__ xw,
                                                        const float* __restrict__ bias,
                                                        float* __restrict__ out) {
    int lane = threadIdx.x & 31;
    int half = lane >> 4;                  // 0 or 1
    int hl   = lane & 15;                  // lane within half-warp
    int i = ((blockIdx.x * blockDim.x + threadIdx.x) >> 5) * 2 + half;  // node per half-warp
    if (i >= N_NODES) return;
    unsigned hmask = 0xFFFFu << (half * 16);

    float acc = fmaf(0.0f, 0.0f, xw[(size_t)i * 16 + hl]);   // self term (dinv-scaled)

    int e0 = g_rowptr[i], e1 = e0 + g_count[i];
    for (int eb = e0; eb < e1; eb += 16) {
        int idx = eb + hl;
        int2 c = make_int2(0, 0);
        if (idx < e1) c = __ldg(&g_csr[idx]);
        int cnt = min(16, e1 - eb);
        for (int j = 0; j < cnt; j++) {
            int   sk = __shfl_sync(hmask, c.x, j, 16);
            float wk = __int_as_float(__shfl_sync(hmask, c.y, j, 16));
            acc = fmaf(wk, __ldg(&xw[(size_t)sk * 16 + hl]), acc);
        }
    }
    float di = g_dinv[i];
    acc = fmaf(acc, di, bias[hl]);

    // log_softmax over the 16 lanes of this half-warp
    float m = acc;
#pragma unroll
    for (int o = 8; o > 0; o >>= 1) m = fmaxf(m, __shfl_xor_sync(hmask, m, o, 16));
    float ee = expf(acc - m);
    float ss = ee;
#pragma unroll
    for (int o = 8; o > 0; o >>= 1) ss += __shfl_xor_sync(hmask, ss, o, 16);
    out[(size_t)i * 16 + hl] = acc - m - logf(ss);
}

// ---------------- launch ----------------
extern "C" void kernel_launch(void* const* d_in, const int* in_sizes, int n_in,
                              void* d_out, int out_size) {
    const float* x    = (const float*)d_in[0];
    const int*   esrc = (const int*)d_in[1];
    const int*   edst = (const int*)d_in[2];
    const float* ew   = (const float*)d_in[3];
    const float* W1   = (const float*)d_in[4];
    const float* b1   = (const float*)d_in[5];
    const float* W2   = (const float*)d_in[6];
    const float* b2   = (const float*)d_in[7];
    const float* W3   = (const float*)d_in[8];
    const float* b3   = (const float*)d_in[9];
    float* out = (float*)d_out;

    __half* p_xw16 = nullptr;
    float *p_xw3 = nullptr, *p_h = nullptr;
    cudaGetSymbolAddress((void**)&p_xw16, g_xw16);
    cudaGetSymbolAddress((void**)&p_xw3,  g_xw3);
    cudaGetSymbolAddress((void**)&p_h,    g_h);

    // Side stream + events, created once on the first (uncaptured) call and
    // reused by every later call so the captured graph topology is identical.
    static cudaStream_t s2 = nullptr;
    static cudaEvent_t evFork = nullptr, evJoin = nullptr;
    if (s2 == nullptr) {
        cudaStreamCreateWithFlags(&s2, cudaStreamNonBlocking);
        cudaEventCreateWithFlags(&evFork, cudaEventDisableTiming);
        cudaEventCreateWithFlags(&evJoin, cudaEventDisableTiming);
    }

    const int NB_NODE = (N_NODES + 255) / 256;       // 196
    const int NB_EDGE = (N_EDGES + 255) / 256;       // 1954
    const int NB_WARP = (N_NODES * 32 + 255) / 256;  // 6250 (warp per node)
    const int NB_HALF = (N_NODES * 16 + 255) / 256;  // 3125 (half-warp per node)
    const int NB_G128 = (N_NODES + 127) / 128;       // 391
    const int NB_G16  = (N_NODES + 255) / 256;       // 196

    // prep chain up to dinv availability
    init_nodes_kernel<<<NB_NODE, 256>>>();
    edge_deg_kernel<<<NB_EDGE, 256>>>(edst, ew);
    alloc_kernel<<<NB_NODE, 256>>>();

    // fork: gemm1 (needs dinv, not CSR) runs concurrent with edge_scatter
    cudaEventRecord(evFork, 0);
    cudaStreamWaitEvent(s2, evFork, 0);
    gemm_tf32<<<NB_G128, 256, 0, s2>>>(x, W1, p_xw16, N_NODES);
    cudaEventRecord(evJoin, s2);

    edge_scatter_kernel<<<NB_EDGE, 256>>>(esrc, edst, ew);
    cudaStreamWaitEvent(0, evJoin, 0);

    // layer 1 aggregate
    agg128_kernel<<<NB_WARP, 256>>>(p_xw16, b1, (float4*)p_h);

    // layer 2
    gemm_tf32<<<NB_G128, 256>>>(p_h, W2, p_xw16, N_NODES);
    agg128_kernel<<<NB_WARP, 256>>>(p_xw16, b2, (float4*)p_h);

    // layer 3
    gemm_f16k<<<NB_G16, 256>>>(p_h, W3, p_xw3, N_NODES);
    agg16_lsm_kernel<<<NB_HALF, 256>>>(p_xw3, b3, out);
}